// round 1
// baseline (speedup 1.0000x reference)
#include <cuda_runtime.h>
#include <cuda_bf16.h>

// Problem constants
#define T_STEPS 1024
#define BATCH   64
#define NK      16
#define HID     20
#define GATES   80
#define CELLS   (BATCH*NK)        // 1024
#define WARPS_PER_CTA 8
#define CTAS    (CELLS/WARPS_PER_CTA)  // 128

// scratch for head outputs: y[0]=1, y[1..1024] = per-cell head value
__device__ float g_y[CELLS + 1];

// ---------- packed f32x2 + MUFU helpers ----------
__device__ __forceinline__ unsigned long long pk2(float lo, float hi) {
    unsigned long long r;
    asm("mov.b64 %0, {%1, %2};" : "=l"(r) : "f"(lo), "f"(hi));
    return r;
}
__device__ __forceinline__ void upk2(unsigned long long v, float& lo, float& hi) {
    asm("mov.b64 {%0, %1}, %2;" : "=f"(lo), "=f"(hi) : "l"(v));
}
__device__ __forceinline__ void fma2(unsigned long long& d, unsigned long long a, unsigned long long b) {
    asm("fma.rn.f32x2 %0, %1, %2, %0;" : "+l"(d) : "l"(a), "l"(b));
}
__device__ __forceinline__ float ex2f(float x) {
    float r; asm("ex2.approx.f32 %0, %1;" : "=f"(r) : "f"(x)); return r;
}
__device__ __forceinline__ float rcpf(float x) {
    float r; asm("rcp.approx.f32 %0, %1;" : "=f"(r) : "f"(x)); return r;
}
// sigmoid(x) = 1 / (1 + 2^(-x*log2e))
__device__ __forceinline__ float sigm(float x) {
    return rcpf(1.0f + ex2f(-1.4426950408889634f * x));
}
// tanh(x) = 1 - 2/(2^(2x*log2e) + 1);  saturates correctly at +-inf
__device__ __forceinline__ float tanhx(float x) {
    float e = ex2f(2.8853900817779268f * x);
    return fmaf(-2.0f, rcpf(e + 1.0f), 1.0f);
}

// ---------- scan kernel: one warp per (k,b) cell ----------
__global__ void __launch_bounds__(WARPS_PER_CTA * 32, 1)
lstm_scan(const float* __restrict__ inp,   // [B,T,K,I]
          const float* __restrict__ w,     // [K*B+1]
          const float* __restrict__ W_ih,  // [K,4H,I]
          const float* __restrict__ W_hh,  // [K,4H,H]
          const float* __restrict__ b_ih,  // [K,4H]
          const float* __restrict__ b_hh,  // [K,4H]
          const float* __restrict__ conv_w,// [H+1]
          const float* __restrict__ conv_b)// scalar
{
    __shared__ __align__(16) float hbuf[2][WARPS_PER_CTA][HID];

    const int wid  = threadIdx.x >> 5;
    const int lane = threadIdx.x & 31;
    const int cell = blockIdx.x * WARPS_PER_CTA + wid;   // = k*64 + b
    const int k    = cell >> 6;
    const int b    = cell & 63;
    const int ju   = (lane < HID) ? lane : (HID - 1);    // lanes 20..31 duplicate unit 19 (masked at stores)

    // ---- preload weights into registers (packed over h-pairs) ----
    unsigned long long whh[4][10];   // [gate][h-pair]
    float wx0[4], wx1[4], wx2[4], bias[4];
#pragma unroll
    for (int g = 0; g < 4; ++g) {
        const int row = k * GATES + g * HID + ju;
        const float* wr = W_hh + (size_t)row * HID;
#pragma unroll
        for (int m = 0; m < 10; ++m) {
            float2 v = *reinterpret_cast<const float2*>(wr + 2 * m);
            whh[g][m] = pk2(v.x, v.y);
        }
        wx0[g] = W_ih[(size_t)row * 3 + 0];
        wx1[g] = W_ih[(size_t)row * 3 + 1];
        wx2[g] = W_ih[(size_t)row * 3 + 2];
        bias[g] = b_ih[row] + b_hh[row];
    }

    // ---- init state ----
    if (lane < HID) hbuf[0][wid][lane] = 0.0f;
    float c = 0.0f, h = 0.0f;

    const float* ip = inp + (size_t)b * (T_STEPS * NK * 3) + k * 3;
    float x0 = __ldg(ip + 0), x1 = __ldg(ip + 1), x2 = __ldg(ip + 2);
    __syncwarp();

    float* rdb = &hbuf[0][wid][0];
    float* wrb = &hbuf[1][wid][0];

    for (int t = 0; t < T_STEPS; ++t) {
        // prefetch next step's input (broadcast load, same addr across lanes)
        const int tn = (t + 1 < T_STEPS) ? (t + 1) : t;
        const float* ipn = ip + (size_t)tn * (NK * 3);
        float nx0 = __ldg(ipn + 0), nx1 = __ldg(ipn + 1), nx2 = __ldg(ipn + 2);

        // gate accumulators: bias + input projection in scalar, then packed recurrent sum
        float s0 = fmaf(wx2[0], x2, fmaf(wx1[0], x1, fmaf(wx0[0], x0, bias[0])));
        float s1 = fmaf(wx2[1], x2, fmaf(wx1[1], x1, fmaf(wx0[1], x0, bias[1])));
        float s2 = fmaf(wx2[2], x2, fmaf(wx1[2], x1, fmaf(wx0[2], x0, bias[2])));
        float s3 = fmaf(wx2[3], x2, fmaf(wx1[3], x1, fmaf(wx0[3], x0, bias[3])));
        unsigned long long a0 = pk2(s0, 0.0f);
        unsigned long long a1 = pk2(s1, 0.0f);
        unsigned long long a2 = pk2(s2, 0.0f);
        unsigned long long a3 = pk2(s3, 0.0f);

#pragma unroll
        for (int m = 0; m < 10; ++m) {
            unsigned long long hp =
                *reinterpret_cast<const unsigned long long*>(rdb + 2 * m);  // LDS.64 broadcast
            fma2(a0, whh[0][m], hp);
            fma2(a1, whh[1][m], hp);
            fma2(a2, whh[2][m], hp);
            fma2(a3, whh[3][m], hp);
        }
        float lo, hi;
        float gi, gf, gg, go;
        upk2(a0, lo, hi); gi = lo + hi;
        upk2(a1, lo, hi); gf = lo + hi;
        upk2(a2, lo, hi); gg = lo + hi;
        upk2(a3, lo, hi); go = lo + hi;

        const float si = sigm(gi);
        const float sf = sigm(gf);
        const float tg = tanhx(gg);
        const float so = sigm(go);
        c = fmaf(sf, c, si * tg);
        h = so * tanhx(c);

        if (lane < HID) wrb[lane] = h;
        __syncwarp();
        float* tmp = rdb; rdb = wrb; wrb = tmp;
        x0 = nx0; x1 = nx1; x2 = nx2;
    }

    // ---- head: y = tanh( dot(h, conv_w[0:20]) + w[1+cell]*conv_w[20] + conv_b ) ----
    float contrib = (lane < HID) ? h * conv_w[lane] : 0.0f;
#pragma unroll
    for (int o = 16; o; o >>= 1)
        contrib += __shfl_xor_sync(0xffffffffu, contrib, o);
    if (lane == 0) {
        float yv = tanhx(contrib + w[1 + cell] * conv_w[HID] + conv_b[0]);
        g_y[1 + cell] = yv;
        if (cell == 0) g_y[0] = 1.0f;   // prepended cash constant
    }
}

// ---------- softmax over 1025 values, single CTA ----------
__global__ void __launch_bounds__(1024, 1)
tail_softmax(float* __restrict__ out)
{
    __shared__ float red[32];
    const int tid  = threadIdx.x;
    const int lane = tid & 31;
    const int wid  = tid >> 5;

    float v  = g_y[tid];
    float v2 = (tid == 0) ? g_y[CELLS] : -3.0e38f;   // element 1024 handled by tid 0

    // block max
    float m = fmaxf(v, v2);
#pragma unroll
    for (int o = 16; o; o >>= 1) m = fmaxf(m, __shfl_xor_sync(0xffffffffu, m, o));
    if (lane == 0) red[wid] = m;
    __syncthreads();
    if (wid == 0) {
        float mm = red[lane];
#pragma unroll
        for (int o = 16; o; o >>= 1) mm = fmaxf(mm, __shfl_xor_sync(0xffffffffu, mm, o));
        red[lane] = mm;
    }
    __syncthreads();
    const float M = red[0];
    __syncthreads();

    float e  = ex2f((v - M) * 1.4426950408889634f);
    float e2 = (tid == 0) ? ex2f((v2 - M) * 1.4426950408889634f) : 0.0f;

    // block sum
    float s = e + e2;
#pragma unroll
    for (int o = 16; o; o >>= 1) s += __shfl_xor_sync(0xffffffffu, s, o);
    if (lane == 0) red[wid] = s;
    __syncthreads();
    if (wid == 0) {
        float ss = red[lane];
#pragma unroll
        for (int o = 16; o; o >>= 1) ss += __shfl_xor_sync(0xffffffffu, ss, o);
        red[lane] = ss;
    }
    __syncthreads();
    const float inv = rcpf(red[0]);

    out[tid] = e * inv;
    if (tid == 0) out[CELLS] = e2 * inv;
}

extern "C" void kernel_launch(void* const* d_in, const int* in_sizes, int n_in,
                              void* d_out, int out_size)
{
    const float* inp    = (const float*)d_in[0];
    const float* w      = (const float*)d_in[1];
    const float* W_ih   = (const float*)d_in[2];
    const float* W_hh   = (const float*)d_in[3];
    const float* b_ih   = (const float*)d_in[4];
    const float* b_hh   = (const float*)d_in[5];
    const float* conv_w = (const float*)d_in[6];
    const float* conv_b = (const float*)d_in[7];
    float* out = (float*)d_out;

    lstm_scan<<<CTAS, WARPS_PER_CTA * 32>>>(inp, w, W_ih, W_hh, b_ih, b_hh, conv_w, conv_b);
    tail_softmax<<<1, 1024>>>(out);
}

// round 3
// speedup vs baseline: 1.4263x; 1.4263x over previous
#include <cuda_runtime.h>
#include <cuda_bf16.h>

// Problem constants
#define T_STEPS 1024
#define BATCH   64
#define NK      16
#define HID     20
#define GATES   80
#define CELLS   (BATCH*NK)        // 1024
#define WARPS_PER_CTA 8
#define CTAS    (CELLS/WARPS_PER_CTA)  // 128
#define ROWF 32                    // padded hbuf row (128B) for LDS.128 alignment

// scratch for head outputs: y[0]=1, y[1..1024] = per-cell head value
__device__ float g_y[CELLS + 1];

typedef unsigned long long ull;

// ---------- packed f32x2 + MUFU helpers ----------
__device__ __forceinline__ ull pk2(float lo, float hi) {
    ull r;
    asm("mov.b64 %0, {%1, %2};" : "=l"(r) : "f"(lo), "f"(hi));
    return r;
}
__device__ __forceinline__ void upk2(ull v, float& lo, float& hi) {
    asm("mov.b64 {%0, %1}, %2;" : "=f"(lo), "=f"(hi) : "l"(v));
}
__device__ __forceinline__ void fma2(ull& d, ull a, ull b) {
    asm("fma.rn.f32x2 %0, %1, %2, %0;" : "+l"(d) : "l"(a), "l"(b));
}
__device__ __forceinline__ ull add2(ull a, ull b) {
    ull r;
    asm("add.rn.f32x2 %0, %1, %2;" : "=l"(r) : "l"(a), "l"(b));
    return r;
}
__device__ __forceinline__ float ex2f(float x) {
    float r; asm("ex2.approx.f32 %0, %1;" : "=f"(r) : "f"(x)); return r;
}
__device__ __forceinline__ float rcpf(float x) {
    float r; asm("rcp.approx.f32 %0, %1;" : "=f"(r) : "f"(x)); return r;
}
// HW tanh (MUFU.TANH, lat ~16)
__device__ __forceinline__ float tanha(float x) {
    float r; asm("tanh.approx.f32 %0, %1;" : "=f"(r) : "f"(x)); return r;
}
// sigmoid(x) = 0.5*tanh(0.5x)+0.5  (3 instrs, ~24 cyc)
__device__ __forceinline__ float sigma(float x) {
    return fmaf(0.5f, tanha(0.5f * x), 0.5f);
}
// precise tanh for the head (off the hot loop)
__device__ __forceinline__ float tanhx(float x) {
    float e = ex2f(2.8853900817779268f * x);
    return fmaf(-2.0f, rcpf(e + 1.0f), 1.0f);
}

// ---------- scan kernel: one warp per (k,b) cell ----------
__global__ void __launch_bounds__(WARPS_PER_CTA * 32, 1)
lstm_scan(const float* __restrict__ inp,   // [B,T,K,I]
          const float* __restrict__ w,     // [K*B+1]
          const float* __restrict__ W_ih,  // [K,4H,I]
          const float* __restrict__ W_hh,  // [K,4H,H]
          const float* __restrict__ b_ih,  // [K,4H]
          const float* __restrict__ b_hh,  // [K,4H]
          const float* __restrict__ conv_w,// [H+1]
          const float* __restrict__ conv_b)// scalar
{
    __shared__ __align__(16) float hbuf[WARPS_PER_CTA][ROWF];

    const int wid  = threadIdx.x >> 5;
    const int lane = threadIdx.x & 31;
    const int cell = blockIdx.x * WARPS_PER_CTA + wid;   // = k*64 + b
    const int k    = cell >> 6;
    const int b    = cell & 63;
    const int ju   = (lane < HID) ? lane : (HID - 1);    // lanes 20..31 duplicate unit 19

    // ---- preload recurrent weights, packed over h-pairs: whh[g][m] = (W[g][2m], W[g][2m+1]) ----
    ull whh[4][10];
    float wx[4][3], bs[4];
#pragma unroll
    for (int g = 0; g < 4; ++g) {
        const int row = k * GATES + g * HID + ju;
        const float* wr = W_hh + (size_t)row * HID;
#pragma unroll
        for (int m = 0; m < 10; ++m) {
            float2 v = *reinterpret_cast<const float2*>(wr + 2 * m);
            whh[g][m] = pk2(v.x, v.y);
        }
        wx[g][0] = W_ih[(size_t)row * 3 + 0];
        wx[g][1] = W_ih[(size_t)row * 3 + 1];
        wx[g][2] = W_ih[(size_t)row * 3 + 2];
        bs[g]    = b_ih[row] + b_hh[row];
    }
    // input weights packed over gate-pairs: wi01[x] = (wx[0][x], wx[1][x]); bias likewise
    ull wi01[3], wi23[3], bp01, bp23;
#pragma unroll
    for (int x = 0; x < 3; ++x) {
        wi01[x] = pk2(wx[0][x], wx[1][x]);
        wi23[x] = pk2(wx[2][x], wx[3][x]);
    }
    bp01 = pk2(bs[0], bs[1]);
    bp23 = pk2(bs[2], bs[3]);

    // shared address of this warp's h row (byte address in shared window)
    const unsigned haddr = (unsigned)__cvta_generic_to_shared(&hbuf[wid][0]);

    // ---- init state ----
    if (lane < HID) hbuf[wid][lane] = 0.0f;
    float c = 0.0f, h = 0.0f;

    const float* ip = inp + (size_t)b * (T_STEPS * NK * 3) + k * 3;
    float x0 = ip[0], x1 = ip[1], x2 = ip[2];
    __syncwarp();

    for (int t = 0; t < T_STEPS; ++t) {
        // prefetch next step's input (broadcast load, same addr across lanes)
        const int tn = (t + 1 < T_STEPS) ? (t + 1) : t;
        const float* ipn = ip + (size_t)tn * (NK * 3);
        const float nx0 = ipn[0], nx1 = ipn[1], nx2 = ipn[2];

        // input projection + bias, packed over gate-pairs (off the h critical path)
        ull xp0 = pk2(x0, x0), xp1 = pk2(x1, x1), xp2 = pk2(x2, x2);
        ull s01 = bp01, s23 = bp23;
        fma2(s01, wi01[0], xp0); fma2(s01, wi01[1], xp1); fma2(s01, wi01[2], xp2);
        fma2(s23, wi23[0], xp0); fma2(s23, wi23[1], xp1); fma2(s23, wi23[2], xp2);
        float s0, s1, s2, s3;
        upk2(s01, s0, s1);
        upk2(s23, s2, s3);

        // recurrent matvec: 2 partial chains per gate (depth 5 each)
        ull a0e = pk2(s0, 0.0f), a0o = 0ULL;
        ull a1e = pk2(s1, 0.0f), a1o = 0ULL;
        ull a2e = pk2(s2, 0.0f), a2o = 0ULL;
        ull a3e = pk2(s3, 0.0f), a3o = 0ULL;

#pragma unroll
        for (int q = 0; q < 5; ++q) {
            ull p0, p1;   // pairs (h[4q],h[4q+1]) and (h[4q+2],h[4q+3])
            asm volatile("ld.shared.v2.b64 {%0, %1}, [%2];"
                         : "=l"(p0), "=l"(p1) : "r"(haddr + 16u * q));
            fma2(a0e, whh[0][2*q],   p0);
            fma2(a1e, whh[1][2*q],   p0);
            fma2(a2e, whh[2][2*q],   p0);
            fma2(a3e, whh[3][2*q],   p0);
            fma2(a0o, whh[0][2*q+1], p1);
            fma2(a1o, whh[1][2*q+1], p1);
            fma2(a2o, whh[2][2*q+1], p1);
            fma2(a3o, whh[3][2*q+1], p1);
        }
        float lo, hi, gi, gf, gg, go;
        upk2(add2(a0e, a0o), lo, hi); gi = lo + hi;
        upk2(add2(a1e, a1o), lo, hi); gf = lo + hi;
        upk2(add2(a2e, a2o), lo, hi); gg = lo + hi;
        upk2(add2(a3e, a3o), lo, hi); go = lo + hi;

        const float si = sigma(gi);
        const float sf = sigma(gf);
        const float tg = tanha(gg);
        const float so = sigma(go);
        c = fmaf(sf, c, si * tg);
        h = so * tanha(c);

        if (lane < HID) hbuf[wid][lane] = h;
        __syncwarp();
        x0 = nx0; x1 = nx1; x2 = nx2;
    }

    // ---- head: y = tanh( dot(h, conv_w[0:20]) + w[1+cell]*conv_w[20] + conv_b ) ----
    float contrib = (lane < HID) ? h * conv_w[lane] : 0.0f;
#pragma unroll
    for (int o = 16; o; o >>= 1)
        contrib += __shfl_xor_sync(0xffffffffu, contrib, o);
    if (lane == 0) {
        float yv = tanhx(contrib + w[1 + cell] * conv_w[HID] + conv_b[0]);
        g_y[1 + cell] = yv;
        if (cell == 0) g_y[0] = 1.0f;   // prepended cash constant
    }
}

// ---------- softmax over 1025 values, single CTA ----------
__global__ void __launch_bounds__(1024, 1)
tail_softmax(float* __restrict__ out)
{
    __shared__ float red[32];
    const int tid  = threadIdx.x;
    const int lane = tid & 31;
    const int wid  = tid >> 5;

    float v  = g_y[tid];
    float v2 = (tid == 0) ? g_y[CELLS] : -3.0e38f;   // element 1024 handled by tid 0

    // block max
    float m = fmaxf(v, v2);
#pragma unroll
    for (int o = 16; o; o >>= 1) m = fmaxf(m, __shfl_xor_sync(0xffffffffu, m, o));
    if (lane == 0) red[wid] = m;
    __syncthreads();
    if (wid == 0) {
        float mm = red[lane];
#pragma unroll
        for (int o = 16; o; o >>= 1) mm = fmaxf(mm, __shfl_xor_sync(0xffffffffu, mm, o));
        red[lane] = mm;
    }
    __syncthreads();
    const float M = red[0];
    __syncthreads();

    float e  = ex2f((v - M) * 1.4426950408889634f);
    float e2 = (tid == 0) ? ex2f((v2 - M) * 1.4426950408889634f) : 0.0f;

    // block sum
    float s = e + e2;
#pragma unroll
    for (int o = 16; o; o >>= 1) s += __shfl_xor_sync(0xffffffffu, s, o);
    if (lane == 0) red[wid] = s;
    __syncthreads();
    if (wid == 0) {
        float ss = red[lane];
#pragma unroll
        for (int o = 16; o; o >>= 1) ss += __shfl_xor_sync(0xffffffffu, ss, o);
        red[lane] = ss;
    }
    __syncthreads();
    const float inv = rcpf(red[0]);

    out[tid] = e * inv;
    if (tid == 0) out[CELLS] = e2 * inv;
}

extern "C" void kernel_launch(void* const* d_in, const int* in_sizes, int n_in,
                              void* d_out, int out_size)
{
    const float* inp    = (const float*)d_in[0];
    const float* w      = (const float*)d_in[1];
    const float* W_ih   = (const float*)d_in[2];
    const float* W_hh   = (const float*)d_in[3];
    const float* b_ih   = (const float*)d_in[4];
    const float* b_hh   = (const float*)d_in[5];
    const float* conv_w = (const float*)d_in[6];
    const float* conv_b = (const float*)d_in[7];
    float* out = (float*)d_out;

    lstm_scan<<<CTAS, WARPS_PER_CTA * 32>>>(inp, w, W_ih, W_hh, b_ih, b_hh, conv_w, conv_b);
    tail_softmax<<<1, 1024>>>(out);
}

// round 4
// speedup vs baseline: 1.4460x; 1.0138x over previous
#include <cuda_runtime.h>
#include <cuda_bf16.h>

// Problem constants
#define T_STEPS 1024
#define NK      16
#define HID     20
#define GATES   80
#define CELLS   1024
#define WARPS_PER_CTA 8
#define NTHREADS (WARPS_PER_CTA * 32)   // 256
#define CTAS    (CELLS / WARPS_PER_CTA) // 128
#define ROWF    32                      // padded hbuf row (128B)
#define XSTRIDE 48                      // NK*3 floats per time step

__device__ float g_y[CELLS + 1];
__device__ int   g_done;

typedef unsigned long long ull;

// ---------- packed f32x2 + MUFU helpers ----------
__device__ __forceinline__ ull pk2(float lo, float hi) {
    ull r;
    asm("mov.b64 %0, {%1, %2};" : "=l"(r) : "f"(lo), "f"(hi));
    return r;
}
__device__ __forceinline__ void upk2(ull v, float& lo, float& hi) {
    asm("mov.b64 {%0, %1}, %2;" : "=f"(lo), "=f"(hi) : "l"(v));
}
__device__ __forceinline__ void fma2(ull& d, ull a, ull b) {
    asm("fma.rn.f32x2 %0, %1, %2, %0;" : "+l"(d) : "l"(a), "l"(b));
}
__device__ __forceinline__ ull add2(ull a, ull b) {
    ull r;
    asm("add.rn.f32x2 %0, %1, %2;" : "=l"(r) : "l"(a), "l"(b));
    return r;
}
__device__ __forceinline__ float ex2f(float x) {
    float r; asm("ex2.approx.f32 %0, %1;" : "=f"(r) : "f"(x)); return r;
}
__device__ __forceinline__ float rcpf(float x) {
    float r; asm("rcp.approx.f32 %0, %1;" : "=f"(r) : "f"(x)); return r;
}
// HW tanh (MUFU.TANH)
__device__ __forceinline__ float tanha(float x) {
    float r; asm("tanh.approx.f32 %0, %1;" : "=f"(r) : "f"(x)); return r;
}
// precise tanh for the head (off the hot loop)
__device__ __forceinline__ float tanhx(float x) {
    float e = ex2f(2.8853900817779268f * x);
    return fmaf(-2.0f, rcpf(e + 1.0f), 1.0f);
}

// ---------- fused kernel: scan + head + (last CTA) softmax ----------
__global__ void __launch_bounds__(NTHREADS, 1)
lstm_fused(const float* __restrict__ inp,   // [B,T,K,I]
           const float* __restrict__ w,     // [K*B+1]
           const float* __restrict__ W_ih,  // [K,4H,I]
           const float* __restrict__ W_hh,  // [K,4H,H]
           const float* __restrict__ b_ih,  // [K,4H]
           const float* __restrict__ b_hh,  // [K,4H]
           const float* __restrict__ conv_w,// [H+1]
           const float* __restrict__ conv_b,// scalar
           float* __restrict__ out)         // [1025]
{
    __shared__ __align__(16) float hbuf[WARPS_PER_CTA][ROWF];
    __shared__ float red[32];
    __shared__ int   s_last;

    const int tid  = threadIdx.x;
    const int wid  = tid >> 5;
    const int lane = tid & 31;
    const int cell = blockIdx.x * WARPS_PER_CTA + wid;   // = k*64 + b
    const int k    = cell >> 6;
    const int b    = cell & 63;
    const int ju   = (lane < HID) ? lane : (HID - 1);    // lanes 20..31 duplicate unit 19

    // ---- preload weights; fold sigmoid's 0.5 pre-scale into gates i,f,o (g unscaled) ----
    ull   whh[4][10];
    float wx[4][3], bs[4];
#pragma unroll
    for (int g = 0; g < 4; ++g) {
        const float sc  = (g == 2) ? 1.0f : 0.5f;
        const int   row = k * GATES + g * HID + ju;
        const float* wr = W_hh + (size_t)row * HID;
#pragma unroll
        for (int m = 0; m < 10; ++m) {
            float2 v = *reinterpret_cast<const float2*>(wr + 2 * m);
            whh[g][m] = pk2(v.x * sc, v.y * sc);
        }
        wx[g][0] = W_ih[(size_t)row * 3 + 0] * sc;
        wx[g][1] = W_ih[(size_t)row * 3 + 1] * sc;
        wx[g][2] = W_ih[(size_t)row * 3 + 2] * sc;
        bs[g]    = (b_ih[row] + b_hh[row]) * sc;
    }

    const unsigned haddr = (unsigned)__cvta_generic_to_shared(&hbuf[wid][0]);

    // ---- init state ----
    if (lane < HID) hbuf[wid][lane] = 0.0f;
    float c = 0.0f, h = 0.0f;

    const float* ip = inp + (size_t)b * (T_STEPS * XSTRIDE) + k * 3;

    // x pipeline (distance-2): xa = raw x(t+1), xb = raw x(t+2); ps = proj(x(t))
    float xa0 = ip[XSTRIDE + 0], xa1 = ip[XSTRIDE + 1], xa2 = ip[XSTRIDE + 2];
    float xb0 = ip[2 * XSTRIDE + 0], xb1 = ip[2 * XSTRIDE + 1], xb2 = ip[2 * XSTRIDE + 2];
    float ps0, ps1, ps2, ps3;
    {
        const float x0 = ip[0], x1 = ip[1], x2 = ip[2];
        ps0 = fmaf(wx[0][2], x2, fmaf(wx[0][1], x1, fmaf(wx[0][0], x0, bs[0])));
        ps1 = fmaf(wx[1][2], x2, fmaf(wx[1][1], x1, fmaf(wx[1][0], x0, bs[1])));
        ps2 = fmaf(wx[2][2], x2, fmaf(wx[2][1], x1, fmaf(wx[2][0], x0, bs[2])));
        ps3 = fmaf(wx[3][2], x2, fmaf(wx[3][1], x1, fmaf(wx[3][0], x0, bs[3])));
    }
    __syncwarp();

#pragma unroll 1
    for (int t = 0; t < T_STEPS; ++t) {
        // prefetch raw x(t+3), consumed as proj two iterations from now
        int tp = t + 3; if (tp > T_STEPS - 1) tp = T_STEPS - 1;
        const float* ipn = ip + (size_t)tp * XSTRIDE;
        const float xc0 = ipn[0], xc1 = ipn[1], xc2 = ipn[2];

        // recurrent matvec: 2 partial chains per gate (depth 5 each), seeded with proj(t)
        ull a0e = pk2(ps0, 0.0f), a0o = 0ULL;
        ull a1e = pk2(ps1, 0.0f), a1o = 0ULL;
        ull a2e = pk2(ps2, 0.0f), a2o = 0ULL;
        ull a3e = pk2(ps3, 0.0f), a3o = 0ULL;

#pragma unroll
        for (int q = 0; q < 5; ++q) {
            ull p0, p1;   // pairs (h[4q],h[4q+1]) and (h[4q+2],h[4q+3])
            asm volatile("ld.shared.v2.b64 {%0, %1}, [%2];"
                         : "=l"(p0), "=l"(p1) : "r"(haddr + 16u * q));
            fma2(a0e, whh[0][2*q],   p0);
            fma2(a1e, whh[1][2*q],   p0);
            fma2(a2e, whh[2][2*q],   p0);
            fma2(a3e, whh[3][2*q],   p0);
            fma2(a0o, whh[0][2*q+1], p1);
            fma2(a1o, whh[1][2*q+1], p1);
            fma2(a2o, whh[2][2*q+1], p1);
            fma2(a3o, whh[3][2*q+1], p1);
        }

        // proj(t+1) from xa — independent work that fills LDS/FMA latency shadows
        const float n0 = fmaf(wx[0][2], xa2, fmaf(wx[0][1], xa1, fmaf(wx[0][0], xa0, bs[0])));
        const float n1 = fmaf(wx[1][2], xa2, fmaf(wx[1][1], xa1, fmaf(wx[1][0], xa0, bs[1])));
        const float n2 = fmaf(wx[2][2], xa2, fmaf(wx[2][1], xa1, fmaf(wx[2][0], xa0, bs[2])));
        const float n3 = fmaf(wx[3][2], xa2, fmaf(wx[3][1], xa1, fmaf(wx[3][0], xa0, bs[3])));

        float lo, hi, gi, gf, gg, go;
        upk2(add2(a0e, a0o), lo, hi); gi = lo + hi;
        upk2(add2(a1e, a1o), lo, hi); gf = lo + hi;
        upk2(add2(a2e, a2o), lo, hi); gg = lo + hi;
        upk2(add2(a3e, a3o), lo, hi); go = lo + hi;

        // gates (0.5 pre-scale folded into weights for i,f,o)
        const float si = fmaf(0.5f, tanha(gi), 0.5f);
        const float sf = fmaf(0.5f, tanha(gf), 0.5f);
        const float tg = tanha(gg);
        const float so = fmaf(0.5f, tanha(go), 0.5f);
        c = fmaf(sf, c, si * tg);
        h = so * tanha(c);

        if (lane < HID) hbuf[wid][lane] = h;
        __syncwarp();

        ps0 = n0; ps1 = n1; ps2 = n2; ps3 = n3;
        xa0 = xb0; xa1 = xb1; xa2 = xb2;
        xb0 = xc0; xb1 = xc1; xb2 = xc2;
    }

    // ---- head: y = tanh( dot(h, conv_w[0:20]) + w[1+cell]*conv_w[20] + conv_b ) ----
    float contrib = (lane < HID) ? h * conv_w[lane] : 0.0f;
#pragma unroll
    for (int o = 16; o; o >>= 1)
        contrib += __shfl_xor_sync(0xffffffffu, contrib, o);
    if (lane == 0) {
        float yv = tanhx(contrib + w[1 + cell] * conv_w[HID] + conv_b[0]);
        g_y[1 + cell] = yv;
        if (cell == 0) g_y[0] = 1.0f;   // prepended cash constant
    }

    // ---- completion protocol (threadFenceReduction pattern) ----
    __threadfence();
    __syncthreads();
    if (tid == 0) {
        int prev = atomicAdd(&g_done, 1);
        s_last = (prev == CTAS - 1);
    }
    __syncthreads();
    if (!s_last) return;
    if (tid == 0) g_done = 0;   // reset for next graph replay

    // ---- last CTA: softmax over y[0..1024] (256 threads, 4 values each + 1 extra) ----
    float v[4];
#pragma unroll
    for (int q = 0; q < 4; ++q) v[q] = __ldcg(&g_y[tid + 256 * q]);
    float vx = (tid == 0) ? __ldcg(&g_y[CELLS]) : -3.0e38f;

    // block max
    float m = fmaxf(fmaxf(fmaxf(v[0], v[1]), fmaxf(v[2], v[3])), vx);
#pragma unroll
    for (int o = 16; o; o >>= 1) m = fmaxf(m, __shfl_xor_sync(0xffffffffu, m, o));
    if (lane == 0) red[wid] = m;
    __syncthreads();
    if (wid == 0) {
        float mm = (lane < WARPS_PER_CTA) ? red[lane] : -3.0e38f;
#pragma unroll
        for (int o = 4; o; o >>= 1) mm = fmaxf(mm, __shfl_xor_sync(0xffffffffu, mm, o));
        if (lane == 0) red[0] = mm;
    }
    __syncthreads();
    const float M = red[0];
    __syncthreads();

    float e[4];
#pragma unroll
    for (int q = 0; q < 4; ++q) e[q] = ex2f((v[q] - M) * 1.4426950408889634f);
    float ex = (tid == 0) ? ex2f((vx - M) * 1.4426950408889634f) : 0.0f;

    // block sum
    float s = e[0] + e[1] + e[2] + e[3] + ex;
#pragma unroll
    for (int o = 16; o; o >>= 1) s += __shfl_xor_sync(0xffffffffu, s, o);
    if (lane == 0) red[wid] = s;
    __syncthreads();
    if (wid == 0) {
        float ss = (lane < WARPS_PER_CTA) ? red[lane] : 0.0f;
#pragma unroll
        for (int o = 4; o; o >>= 1) ss += __shfl_xor_sync(0xffffffffu, ss, o);
        if (lane == 0) red[0] = ss;
    }
    __syncthreads();
    const float inv = rcpf(red[0]);

#pragma unroll
    for (int q = 0; q < 4; ++q) out[tid + 256 * q] = e[q] * inv;
    if (tid == 0) out[CELLS] = ex * inv;
}

extern "C" void kernel_launch(void* const* d_in, const int* in_sizes, int n_in,
                              void* d_out, int out_size)
{
    const float* inp    = (const float*)d_in[0];
    const float* w      = (const float*)d_in[1];
    const float* W_ih   = (const float*)d_in[2];
    const float* W_hh   = (const float*)d_in[3];
    const float* b_ih   = (const float*)d_in[4];
    const float* b_hh   = (const float*)d_in[5];
    const float* conv_w = (const float*)d_in[6];
    const float* conv_b = (const float*)d_in[7];
    float* out = (float*)d_out;

    lstm_fused<<<CTAS, NTHREADS>>>(inp, w, W_ih, W_hh, b_ih, b_hh,
                                   conv_w, conv_b, out);
}